// round 2
// baseline (speedup 1.0000x reference)
#include <cuda_runtime.h>
#include <math.h>

#define N_NODES 10000
#define N_EDGES 160000
#define FIN     256
#define HID     128
#define H1      5
#define H3      3
#define NGRAPH  64
#define NCLS    10
#define D1      (H1*HID)   /* 640 */
#define D3      (H3*HID)   /* 384 */
#define ETOT    (N_EDGES + N_NODES)

// ---------------- device scratch (no allocation allowed) ----------------
__device__ float g_h  [N_NODES * D1];
__device__ float g_x1 [N_NODES * D1];
__device__ float g_x2 [N_NODES * D1];
__device__ float g_agg[N_NODES * D1];
__device__ float g_als[N_NODES * H1];
__device__ float g_ald[N_NODES * H1];
__device__ float g_m  [N_NODES * H1];
__device__ float g_s  [N_NODES * H1];
__device__ float g_x3 [N_NODES * HID];
__device__ float g_pool[NGRAPH * HID];
__device__ float g_cnt [NGRAPH];

// ---------------- generic fill ----------------
__global__ void fill_kernel(float* p, float v, int n) {
    int i = blockIdx.x * blockDim.x + threadIdx.x;
    if (i < n) p[i] = v;
}

// ---------------- tiled fp32 GEMM: C[M,Nd] = A[M,K] @ B[K,Nd] ----------------
// BM=BN=64, BK=16, 256 threads, 4x4 micro-tile. K, Nd divisible by 16/64.
__global__ void sgemm_kernel(const float* __restrict__ A, const float* __restrict__ B,
                             float* __restrict__ C, int M, int K, int Nd) {
    __shared__ float As[16][68];
    __shared__ float Bs[16][68];
    int tid = threadIdx.x;
    int tx = tid & 15;        // 0..15 -> N
    int ty = tid >> 4;        // 0..15 -> M
    int rowBase = blockIdx.y * 64;
    int colBase = blockIdx.x * 64;
    float acc[4][4] = {};
    for (int k0 = 0; k0 < K; k0 += 16) {
        // A tile: 64 rows x 16 k
        #pragma unroll
        for (int i = tid; i < 64 * 16; i += 256) {
            int r = i >> 4, c = i & 15;
            int gr = rowBase + r;
            As[c][r] = (gr < M) ? A[(size_t)gr * K + k0 + c] : 0.f;
        }
        // B tile: 16 k x 64 cols
        #pragma unroll
        for (int i = tid; i < 16 * 64; i += 256) {
            int r = i >> 6, c = i & 63;
            Bs[r][c] = B[(size_t)(k0 + r) * Nd + colBase + c];
        }
        __syncthreads();
        #pragma unroll
        for (int k = 0; k < 16; k++) {
            float a[4], b[4];
            #pragma unroll
            for (int i = 0; i < 4; i++) a[i] = As[k][ty * 4 + i];
            #pragma unroll
            for (int j = 0; j < 4; j++) b[j] = Bs[k][tx * 4 + j];
            #pragma unroll
            for (int i = 0; i < 4; i++)
                #pragma unroll
                for (int j = 0; j < 4; j++)
                    acc[i][j] += a[i] * b[j];
        }
        __syncthreads();
    }
    #pragma unroll
    for (int i = 0; i < 4; i++) {
        int gr = rowBase + ty * 4 + i;
        if (gr < M) {
            #pragma unroll
            for (int j = 0; j < 4; j++)
                C[(size_t)gr * Nd + colBase + tx * 4 + j] = acc[i][j];
        }
    }
}

// ---------------- per-(node,head) attention logits ----------------
// one warp per (node, head): als = <h[n,h,:], a_src[h,:]>, ald likewise
__global__ void attn_logits_kernel(const float* __restrict__ h,
                                   const float* __restrict__ a_s,
                                   const float* __restrict__ a_d,
                                   float* __restrict__ als, float* __restrict__ ald,
                                   int N, int H) {
    int w = (blockIdx.x * blockDim.x + threadIdx.x) >> 5;
    int lane = threadIdx.x & 31;
    if (w >= N * H) return;
    int n = w / H, hh = w % H;
    const float* hp = h + ((size_t)n * H + hh) * HID;
    float s1 = 0.f, s2 = 0.f;
    #pragma unroll
    for (int c = lane; c < HID; c += 32) {
        float v = hp[c];
        s1 += v * a_s[hh * HID + c];
        s2 += v * a_d[hh * HID + c];
    }
    #pragma unroll
    for (int o = 16; o > 0; o >>= 1) {
        s1 += __shfl_xor_sync(0xffffffffu, s1, o);
        s2 += __shfl_xor_sync(0xffffffffu, s2, o);
    }
    if (lane == 0) { als[w] = s1; ald[w] = s2; }
}

__device__ __forceinline__ void atomicMaxFloat(float* addr, float v) {
    if (v >= 0.f) atomicMax((int*)addr, __float_as_int(v));
    else          atomicMin((unsigned int*)addr, __float_as_uint(v));
}

// ---------------- per-(edge,head) max for stable softmax ----------------
__global__ void edge_max_kernel(const int* __restrict__ src, const int* __restrict__ dst,
                                const float* __restrict__ als, const float* __restrict__ ald,
                                float* __restrict__ m, int H) {
    int i = blockIdx.x * blockDim.x + threadIdx.x;
    if (i >= ETOT * H) return;
    int hh = i % H, ed = i / H;
    int s, d;
    if (ed < N_EDGES) { s = src[ed]; d = dst[ed]; } else { s = d = ed - N_EDGES; }
    float v = als[s * H + hh] + ald[d * H + hh];
    v = v > 0.f ? v : 0.2f * v;   // leaky_relu(0.2)
    atomicMaxFloat(&m[d * H + hh], v);
}

// ---------------- fused exp + weighted scatter-add ----------------
// one warp per edge; loops heads; thread c4 = lane handles 4 channels (float4 gather)
__global__ void edge_agg_kernel(const int* __restrict__ src, const int* __restrict__ dst,
                                const float* __restrict__ als, const float* __restrict__ ald,
                                const float* __restrict__ m,
                                const float* __restrict__ h,
                                float* __restrict__ ssum, float* __restrict__ agg, int H) {
    int w = (blockIdx.x * blockDim.x + threadIdx.x) >> 5;
    int lane = threadIdx.x & 31;
    if (w >= ETOT) return;
    int s, d;
    if (w < N_EDGES) { s = src[w]; d = dst[w]; } else { s = d = w - N_EDGES; }
    for (int hh = 0; hh < H; hh++) {
        float v = als[s * H + hh] + ald[d * H + hh];
        v = v > 0.f ? v : 0.2f * v;
        float ex = __expf(v - m[d * H + hh]);
        if (lane == 0) atomicAdd(&ssum[d * H + hh], ex);
        const float4* hp = (const float4*)(h + ((size_t)s * H + hh) * HID);
        float4 hv = hp[lane];
        float* op = agg + ((size_t)d * H + hh) * HID + lane * 4;
        atomicAdd(op + 0, ex * hv.x);
        atomicAdd(op + 1, ex * hv.y);
        atomicAdd(op + 2, ex * hv.z);
        atomicAdd(op + 3, ex * hv.w);
    }
}

// ---------------- layer finalizers ----------------
__global__ void finalize1_kernel(const float* __restrict__ agg, const float* __restrict__ ssum,
                                 const float* __restrict__ b, float* __restrict__ x1) {
    int i = blockIdx.x * blockDim.x + threadIdx.x;
    if (i >= N_NODES * D1) return;
    int n = i / D1, r = i % D1, hh = r / HID;
    float v = agg[i] / (ssum[n * H1 + hh] + 1e-16f) + b[r];
    x1[i] = v > 0.f ? v : (expf(v) - 1.f);   // ELU
}

__global__ void finalize2_kernel(const float* __restrict__ agg, const float* __restrict__ ssum,
                                 const float* __restrict__ b, const float* __restrict__ x1,
                                 float* __restrict__ x2) {
    int i = blockIdx.x * blockDim.x + threadIdx.x;
    if (i >= N_NODES * D1) return;
    int n = i / D1, r = i % D1, hh = r / HID;
    float v = x1[i] + agg[i] / (ssum[n * H1 + hh] + 1e-16f) + b[r];
    x2[i] = v > 0.f ? v : (expf(v) - 1.f);
}

__global__ void finalize3_kernel(const float* __restrict__ agg, const float* __restrict__ ssum,
                                 const float* __restrict__ b, float* __restrict__ x3) {
    int i = blockIdx.x * blockDim.x + threadIdx.x;
    if (i >= N_NODES * HID) return;
    int n = i / HID, c = i % HID;
    float acc = 0.f;
    #pragma unroll
    for (int hh = 0; hh < H3; hh++)
        acc += agg[((size_t)n * H3 + hh) * HID + c] / (ssum[n * H3 + hh] + 1e-16f);
    x3[i] = acc * (1.f / 3.f) + b[c];
}

// ---------------- global mean pool ----------------
__global__ void pool_kernel(const float* __restrict__ x3, const int* __restrict__ batch,
                            float* __restrict__ pool, float* __restrict__ cnt) {
    int i = blockIdx.x * blockDim.x + threadIdx.x;
    if (i >= N_NODES * HID) return;
    int n = i / HID, c = i % HID;
    int g = batch[n];
    atomicAdd(&pool[(size_t)g * HID + c], x3[i]);
    if (c == 0) atomicAdd(&cnt[g], 1.f);
}

// ---------------- classifier head + log_softmax ----------------
__global__ void head_kernel(const float* __restrict__ pool, const float* __restrict__ cnt,
                            const float* __restrict__ Wc, const float* __restrict__ bc,
                            float* __restrict__ out) {
    __shared__ float sl[NGRAPH][NCLS];
    __shared__ float lse[NGRAPH];
    int tid = threadIdx.x;               // 640 threads
    int g = tid / NCLS, k = tid % NCLS;
    float c = cnt[g]; c = c < 1.f ? 1.f : c;
    float acc = bc[k];
    #pragma unroll 8
    for (int j = 0; j < HID; j++)
        acc += (pool[(size_t)g * HID + j] / c) * Wc[j * NCLS + k];
    sl[g][k] = acc;
    out[g * NCLS + k] = acc;             // logits
    __syncthreads();
    if (k == 0) {
        float mx = sl[g][0];
        #pragma unroll
        for (int j = 1; j < NCLS; j++) mx = fmaxf(mx, sl[g][j]);
        float s = 0.f;
        #pragma unroll
        for (int j = 0; j < NCLS; j++) s += expf(sl[g][j] - mx);
        lse[g] = mx + logf(s);
    }
    __syncthreads();
    out[NGRAPH * NCLS + g * NCLS + k] = sl[g][k] - lse[g];   // log_softmax
}

// ---------------- one GAT layer (shared machinery) ----------------
static void run_gat(const float* X, int Din, int H, const float* W,
                    const float* as_, const float* ad_,
                    const int* src, const int* dst,
                    float* h, float* agg, float* als, float* ald, float* m, float* ssum) {
    int D = H * HID;
    dim3 grid(D / 64, (N_NODES + 63) / 64);
    sgemm_kernel<<<grid, 256>>>(X, W, h, N_NODES, Din, D);
    attn_logits_kernel<<<(N_NODES * H * 32 + 255) / 256, 256>>>(h, as_, ad_, als, ald, N_NODES, H);
    fill_kernel<<<(N_NODES * D + 255) / 256, 256>>>(agg, 0.f, N_NODES * D);
    fill_kernel<<<(N_NODES * H + 255) / 256, 256>>>(m, -1e30f, N_NODES * H);
    fill_kernel<<<(N_NODES * H + 255) / 256, 256>>>(ssum, 0.f, N_NODES * H);
    edge_max_kernel<<<(ETOT * H + 255) / 256, 256>>>(src, dst, als, ald, m, H);
    edge_agg_kernel<<<(ETOT * 32 + 255) / 256, 256>>>(src, dst, als, ald, m, h, ssum, agg, H);
}

extern "C" void kernel_launch(void* const* d_in, const int* in_sizes, int n_in,
                              void* d_out, int out_size) {
    const float* x     = (const float*)d_in[0];
    const int*   ei    = (const int*)  d_in[1];
    const int*   batch = (const int*)  d_in[2];
    const float* W1  = (const float*)d_in[3];
    const float* a1s = (const float*)d_in[4];
    const float* a1d = (const float*)d_in[5];
    const float* b1  = (const float*)d_in[6];
    const float* W2  = (const float*)d_in[7];
    const float* a2s = (const float*)d_in[8];
    const float* a2d = (const float*)d_in[9];
    const float* b2  = (const float*)d_in[10];
    const float* W3  = (const float*)d_in[11];
    const float* a3s = (const float*)d_in[12];
    const float* a3d = (const float*)d_in[13];
    const float* b3  = (const float*)d_in[14];
    const float* Wc  = (const float*)d_in[15];
    const float* bc  = (const float*)d_in[16];
    float* out = (float*)d_out;

    float *h, *x1, *x2, *agg, *als, *ald, *m, *s, *x3, *pool, *cnt;
    cudaGetSymbolAddress((void**)&h,    g_h);
    cudaGetSymbolAddress((void**)&x1,   g_x1);
    cudaGetSymbolAddress((void**)&x2,   g_x2);
    cudaGetSymbolAddress((void**)&agg,  g_agg);
    cudaGetSymbolAddress((void**)&als,  g_als);
    cudaGetSymbolAddress((void**)&ald,  g_ald);
    cudaGetSymbolAddress((void**)&m,    g_m);
    cudaGetSymbolAddress((void**)&s,    g_s);
    cudaGetSymbolAddress((void**)&x3,   g_x3);
    cudaGetSymbolAddress((void**)&pool, g_pool);
    cudaGetSymbolAddress((void**)&cnt,  g_cnt);

    const int* src = ei;
    const int* dst = ei + N_EDGES;

    // Layer 1: x1 = elu(gat(x))
    run_gat(x, FIN, H1, W1, a1s, a1d, src, dst, h, agg, als, ald, m, s);
    finalize1_kernel<<<(N_NODES * D1 + 255) / 256, 256>>>(agg, s, b1, x1);

    // Layer 2: x2 = elu(x1 + gat(x1))
    run_gat(x1, D1, H1, W2, a2s, a2d, src, dst, h, agg, als, ald, m, s);
    finalize2_kernel<<<(N_NODES * D1 + 255) / 256, 256>>>(agg, s, b2, x1, x2);

    // Layer 3: x3 = mean-head gat(x2)
    run_gat(x2, D1, H3, W3, a3s, a3d, src, dst, h, agg, als, ald, m, s);
    finalize3_kernel<<<(N_NODES * HID + 255) / 256, 256>>>(agg, s, b3, x3);

    // Global mean pool + head
    fill_kernel<<<(NGRAPH * HID + 255) / 256, 256>>>(pool, 0.f, NGRAPH * HID);
    fill_kernel<<<(NGRAPH + 255) / 256, 256>>>(cnt, 0.f, NGRAPH);
    pool_kernel<<<(N_NODES * HID + 255) / 256, 256>>>(x3, batch, pool, cnt);
    head_kernel<<<1, NGRAPH * NCLS>>>(pool, cnt, Wc, bc, out);
}

// round 7
// speedup vs baseline: 1.9479x; 1.9479x over previous
#include <cuda_runtime.h>
#include <math.h>

#define N_NODES 10000
#define N_EDGES 160000
#define FIN     256
#define HID     128
#define H1      5
#define H3      3
#define NGRAPH  64
#define NCLS    10
#define D1      (H1*HID)   /* 640 */
#define ETOT    (N_EDGES + N_NODES)

// ---------------- device scratch (no allocation allowed) ----------------
__device__ float g_h  [N_NODES * D1];
__device__ float g_x1 [N_NODES * D1];
__device__ float g_x2 [N_NODES * D1];
__device__ float g_agg[N_NODES * D1];
__device__ float g_als[N_NODES * H1];
__device__ float g_ald[N_NODES * H1];
__device__ float g_x3 [N_NODES * HID];
__device__ float g_pool[NGRAPH * HID];
__device__ float g_cnt [NGRAPH];
// CSR scratch
__device__ int g_deg[N_NODES];
__device__ int g_off[N_NODES + 1];
__device__ int g_cur[N_NODES];
__device__ int g_col[ETOT];

// ---------------- fills ----------------
__global__ void fill_kernel(float* p, float v, int n) {
    int i = blockIdx.x * blockDim.x + threadIdx.x;
    if (i < n) p[i] = v;
}
__global__ void fill_int_kernel(int* p, int v, int n) {
    int i = blockIdx.x * blockDim.x + threadIdx.x;
    if (i < n) p[i] = v;
}

// ---------------- CSR build: histogram -> scan -> scatter ----------------
__global__ void hist_kernel(const int* __restrict__ dst, int* __restrict__ deg) {
    int i = blockIdx.x * blockDim.x + threadIdx.x;
    if (i >= ETOT) return;
    int d = (i < N_EDGES) ? dst[i] : (i - N_EDGES);
    atomicAdd(&deg[d], 1);
}

__global__ void scan_kernel(const int* __restrict__ deg, int* __restrict__ off,
                            int* __restrict__ cur) {
    __shared__ int part[1024];
    int t = threadIdx.x;
    const int CH = (N_NODES + 1023) / 1024;   // 10
    int base = t * CH;
    int s = 0;
    for (int i = 0; i < CH; i++) {
        int idx = base + i;
        if (idx < N_NODES) s += deg[idx];
    }
    part[t] = s;
    __syncthreads();
    for (int o = 1; o < 1024; o <<= 1) {
        int v = (t >= o) ? part[t - o] : 0;
        __syncthreads();
        part[t] += v;
        __syncthreads();
    }
    int run = (t == 0) ? 0 : part[t - 1];
    for (int i = 0; i < CH; i++) {
        int idx = base + i;
        if (idx < N_NODES) {
            off[idx] = run;
            cur[idx] = run;
            run += deg[idx];
        }
    }
    if (t == 1023) off[N_NODES] = ETOT;
}

__global__ void scatter_kernel(const int* __restrict__ src, const int* __restrict__ dst,
                               int* __restrict__ cur, int* __restrict__ colarr) {
    int i = blockIdx.x * blockDim.x + threadIdx.x;
    if (i >= ETOT) return;
    int d, s;
    if (i < N_EDGES) { s = src[i]; d = dst[i]; } else { s = d = i - N_EDGES; }
    int slot = atomicAdd(&cur[d], 1);
    colarr[slot] = s;
}

// ---------------- 128x128x8 fp32 GEMM, 8x8 micro-tile ----------------
// C[M,Nd] = A[M,K] @ B[K,Nd]; Nd % 128 == 0, K % 8 == 0.
__global__ void __launch_bounds__(256, 2)
sgemm128_kernel(const float* __restrict__ A, const float* __restrict__ B,
                float* __restrict__ C, int M, int K, int Nd) {
    __shared__ float As[8][132];
    __shared__ float Bs[8][132];
    int tid = threadIdx.x;
    int rowBase = blockIdx.y * 128;
    int colBase = blockIdx.x * 128;
    int ty = tid >> 4;        // 0..15 -> 8 rows each
    int tx = tid & 15;        // 0..15 -> 8 cols each

    // A load mapping: row = tid/2 (0..127), k-quad = (tid&1)*4
    int arow = tid >> 1;
    int akq  = (tid & 1) * 4;
    // B load mapping: krow = tid/32 (0..7), col4 = (tid&31)*4
    int bkr  = tid >> 5;
    int bc4  = (tid & 31) * 4;

    float acc[8][8] = {};
    for (int k0 = 0; k0 < K; k0 += 8) {
        int gr = rowBase + arow;
        float4 a4 = make_float4(0.f, 0.f, 0.f, 0.f);
        if (gr < M) a4 = *(const float4*)&A[(size_t)gr * K + k0 + akq];
        As[akq + 0][arow] = a4.x;
        As[akq + 1][arow] = a4.y;
        As[akq + 2][arow] = a4.z;
        As[akq + 3][arow] = a4.w;
        float4 b4 = *(const float4*)&B[(size_t)(k0 + bkr) * Nd + colBase + bc4];
        *(float4*)&Bs[bkr][bc4] = b4;
        __syncthreads();
        #pragma unroll
        for (int k = 0; k < 8; k++) {
            float a[8], b[8];
            *(float4*)&a[0] = *(const float4*)&As[k][ty * 8];
            *(float4*)&a[4] = *(const float4*)&As[k][ty * 8 + 4];
            *(float4*)&b[0] = *(const float4*)&Bs[k][tx * 8];
            *(float4*)&b[4] = *(const float4*)&Bs[k][tx * 8 + 4];
            #pragma unroll
            for (int i = 0; i < 8; i++)
                #pragma unroll
                for (int j = 0; j < 8; j++)
                    acc[i][j] += a[i] * b[j];
        }
        __syncthreads();
    }
    #pragma unroll
    for (int i = 0; i < 8; i++) {
        int gr = rowBase + ty * 8 + i;
        if (gr < M) {
            float* cp = &C[(size_t)gr * Nd + colBase + tx * 8];
            *(float4*)&cp[0] = *(float4*)&acc[i][0];
            *(float4*)&cp[4] = *(float4*)&acc[i][4];
        }
    }
}

// ---------------- per-(node,head) attention logits ----------------
__global__ void attn_logits_kernel(const float* __restrict__ h,
                                   const float* __restrict__ a_s,
                                   const float* __restrict__ a_d,
                                   float* __restrict__ als, float* __restrict__ ald,
                                   int N, int H) {
    int w = (blockIdx.x * blockDim.x + threadIdx.x) >> 5;
    int lane = threadIdx.x & 31;
    if (w >= N * H) return;
    int n = w / H, hh = w % H;
    const float* hp = h + ((size_t)n * H + hh) * HID;
    float s1 = 0.f, s2 = 0.f;
    #pragma unroll
    for (int c = lane; c < HID; c += 32) {
        float v = hp[c];
        s1 += v * a_s[hh * HID + c];
        s2 += v * a_d[hh * HID + c];
    }
    #pragma unroll
    for (int o = 16; o > 0; o >>= 1) {
        s1 += __shfl_xor_sync(0xffffffffu, s1, o);
        s2 += __shfl_xor_sync(0xffffffffu, s2, o);
    }
    if (lane == 0) { als[w] = s1; ald[w] = s2; }
}

// ---------------- CSR softmax aggregation: one warp per node ----------------
// agg[n,h,:] = sum_j exp(v_j - max) * h[col_j, h, :] / (sum_j exp + 1e-16)
__global__ void gat_agg_kernel(const int* __restrict__ off, const int* __restrict__ col,
                               const float* __restrict__ als, const float* __restrict__ ald,
                               const float* __restrict__ h, float* __restrict__ agg, int H) {
    int node = (blockIdx.x * blockDim.x + threadIdx.x) >> 5;
    int lane = threadIdx.x & 31;
    if (node >= N_NODES) return;
    int beg = off[node], end = off[node + 1];
    for (int hh = 0; hh < H; hh++) {
        float ald_d = __ldg(&ald[node * H + hh]);
        // pass 1: max (lane-strided)
        float mx = -1e30f;
        for (int j = beg + lane; j < end; j += 32) {
            float v = __ldg(&als[col[j] * H + hh]) + ald_d;
            v = v > 0.f ? v : 0.2f * v;
            mx = fmaxf(mx, v);
        }
        #pragma unroll
        for (int o = 16; o > 0; o >>= 1)
            mx = fmaxf(mx, __shfl_xor_sync(0xffffffffu, mx, o));
        // pass 2: sequential edges; lane owns 4 channels
        float4 acc = make_float4(0.f, 0.f, 0.f, 0.f);
        float ssum = 0.f;
        for (int j = beg; j < end; j++) {
            int s = col[j];
            float v = __ldg(&als[s * H + hh]) + ald_d;
            v = v > 0.f ? v : 0.2f * v;
            float ex = __expf(v - mx);
            ssum += ex;
            float4 hv = ((const float4*)(h + ((size_t)s * H + hh) * HID))[lane];
            acc.x += ex * hv.x;
            acc.y += ex * hv.y;
            acc.z += ex * hv.z;
            acc.w += ex * hv.w;
        }
        float inv = 1.f / (ssum + 1e-16f);
        float4 o4 = make_float4(acc.x * inv, acc.y * inv, acc.z * inv, acc.w * inv);
        ((float4*)(agg + ((size_t)node * H + hh) * HID))[lane] = o4;
    }
}

// ---------------- layer finalizers (agg already normalized) ----------------
__global__ void finalize1_kernel(const float* __restrict__ agg,
                                 const float* __restrict__ b, float* __restrict__ x1) {
    int i = blockIdx.x * blockDim.x + threadIdx.x;
    if (i >= N_NODES * D1) return;
    int r = i % D1;
    float v = agg[i] + b[r];
    x1[i] = v > 0.f ? v : (expf(v) - 1.f);   // ELU
}

__global__ void finalize2_kernel(const float* __restrict__ agg,
                                 const float* __restrict__ b, const float* __restrict__ x1,
                                 float* __restrict__ x2) {
    int i = blockIdx.x * blockDim.x + threadIdx.x;
    if (i >= N_NODES * D1) return;
    int r = i % D1;
    float v = x1[i] + agg[i] + b[r];
    x2[i] = v > 0.f ? v : (expf(v) - 1.f);
}

__global__ void finalize3_kernel(const float* __restrict__ agg,
                                 const float* __restrict__ b, float* __restrict__ x3) {
    int i = blockIdx.x * blockDim.x + threadIdx.x;
    if (i >= N_NODES * HID) return;
    int n = i / HID, c = i % HID;
    float acc = 0.f;
    #pragma unroll
    for (int hh = 0; hh < H3; hh++)
        acc += agg[((size_t)n * H3 + hh) * HID + c];
    x3[i] = acc * (1.f / 3.f) + b[c];
}

// ---------------- global mean pool ----------------
__global__ void pool_kernel(const float* __restrict__ x3, const int* __restrict__ batch,
                            float* __restrict__ pool, float* __restrict__ cnt) {
    int i = blockIdx.x * blockDim.x + threadIdx.x;
    if (i >= N_NODES * HID) return;
    int n = i / HID, c = i % HID;
    int g = batch[n];
    atomicAdd(&pool[(size_t)g * HID + c], x3[i]);
    if (c == 0) atomicAdd(&cnt[g], 1.f);
}

// ---------------- classifier head + log_softmax ----------------
__global__ void head_kernel(const float* __restrict__ pool, const float* __restrict__ cnt,
                            const float* __restrict__ Wc, const float* __restrict__ bc,
                            float* __restrict__ out) {
    __shared__ float sl[NGRAPH][NCLS];
    __shared__ float lse[NGRAPH];
    int tid = threadIdx.x;               // 640 threads
    int g = tid / NCLS, k = tid % NCLS;
    float c = cnt[g]; c = c < 1.f ? 1.f : c;
    float acc = bc[k];
    #pragma unroll 8
    for (int j = 0; j < HID; j++)
        acc += (pool[(size_t)g * HID + j] / c) * Wc[j * NCLS + k];
    sl[g][k] = acc;
    out[g * NCLS + k] = acc;             // logits
    __syncthreads();
    if (k == 0) {
        float mx = sl[g][0];
        #pragma unroll
        for (int j = 1; j < NCLS; j++) mx = fmaxf(mx, sl[g][j]);
        float s = 0.f;
        #pragma unroll
        for (int j = 0; j < NCLS; j++) s += expf(sl[g][j] - mx);
        lse[g] = mx + logf(s);
    }
    __syncthreads();
    out[NGRAPH * NCLS + g * NCLS + k] = sl[g][k] - lse[g];   // log_softmax
}

// ---------------- one GAT layer ----------------
static void run_gat(const float* X, int Din, int H, const float* W,
                    const float* as_, const float* ad_,
                    const int* off, const int* col,
                    float* h, float* agg, float* als, float* ald) {
    int D = H * HID;
    dim3 grid(D / 128, (N_NODES + 127) / 128);
    sgemm128_kernel<<<grid, 256>>>(X, W, h, N_NODES, Din, D);
    attn_logits_kernel<<<(N_NODES * H * 32 + 255) / 256, 256>>>(h, as_, ad_, als, ald, N_NODES, H);
    gat_agg_kernel<<<(N_NODES * 32 + 255) / 256, 256>>>(off, col, als, ald, h, agg, H);
}

extern "C" void kernel_launch(void* const* d_in, const int* in_sizes, int n_in,
                              void* d_out, int out_size) {
    const float* x     = (const float*)d_in[0];
    const int*   ei    = (const int*)  d_in[1];
    const int*   batch = (const int*)  d_in[2];
    const float* W1  = (const float*)d_in[3];
    const float* a1s = (const float*)d_in[4];
    const float* a1d = (const float*)d_in[5];
    const float* b1  = (const float*)d_in[6];
    const float* W2  = (const float*)d_in[7];
    const float* a2s = (const float*)d_in[8];
    const float* a2d = (const float*)d_in[9];
    const float* b2  = (const float*)d_in[10];
    const float* W3  = (const float*)d_in[11];
    const float* a3s = (const float*)d_in[12];
    const float* a3d = (const float*)d_in[13];
    const float* b3  = (const float*)d_in[14];
    const float* Wc  = (const float*)d_in[15];
    const float* bc  = (const float*)d_in[16];
    float* out = (float*)d_out;

    float *h, *x1, *x2, *agg, *als, *ald, *x3, *pool, *cnt;
    int *deg, *off, *cur, *col;
    cudaGetSymbolAddress((void**)&h,    g_h);
    cudaGetSymbolAddress((void**)&x1,   g_x1);
    cudaGetSymbolAddress((void**)&x2,   g_x2);
    cudaGetSymbolAddress((void**)&agg,  g_agg);
    cudaGetSymbolAddress((void**)&als,  g_als);
    cudaGetSymbolAddress((void**)&ald,  g_ald);
    cudaGetSymbolAddress((void**)&x3,   g_x3);
    cudaGetSymbolAddress((void**)&pool, g_pool);
    cudaGetSymbolAddress((void**)&cnt,  g_cnt);
    cudaGetSymbolAddress((void**)&deg,  g_deg);
    cudaGetSymbolAddress((void**)&off,  g_off);
    cudaGetSymbolAddress((void**)&cur,  g_cur);
    cudaGetSymbolAddress((void**)&col,  g_col);

    const int* src = ei;
    const int* dst = ei + N_EDGES;

    // ---- CSR build (by destination) ----
    fill_int_kernel<<<(N_NODES + 255) / 256, 256>>>(deg, 0, N_NODES);
    hist_kernel<<<(ETOT + 255) / 256, 256>>>(dst, deg);
    scan_kernel<<<1, 1024>>>(deg, off, cur);
    scatter_kernel<<<(ETOT + 255) / 256, 256>>>(src, dst, cur, col);

    // Layer 1: x1 = elu(gat(x))
    run_gat(x, FIN, H1, W1, a1s, a1d, off, col, h, agg, als, ald);
    finalize1_kernel<<<(N_NODES * D1 + 255) / 256, 256>>>(agg, b1, x1);

    // Layer 2: x2 = elu(x1 + gat(x1))
    run_gat(x1, D1, H1, W2, a2s, a2d, off, col, h, agg, als, ald);
    finalize2_kernel<<<(N_NODES * D1 + 255) / 256, 256>>>(agg, b2, x1, x2);

    // Layer 3: x3 = mean-head gat(x2)
    run_gat(x2, D1, H3, W3, a3s, a3d, off, col, h, agg, als, ald);
    finalize3_kernel<<<(N_NODES * HID + 255) / 256, 256>>>(agg, b3, x3);

    // Global mean pool + head
    fill_kernel<<<(NGRAPH * HID + 255) / 256, 256>>>(pool, 0.f, NGRAPH * HID);
    fill_kernel<<<(NGRAPH + 255) / 256, 256>>>(cnt, 0.f, NGRAPH);
    pool_kernel<<<(N_NODES * HID + 255) / 256, 256>>>(x3, batch, pool, cnt);
    head_kernel<<<1, NGRAPH * NCLS>>>(pool, cnt, Wc, bc, out);
}

// round 8
// speedup vs baseline: 3.6285x; 1.8628x over previous
#include <cuda_runtime.h>
#include <math.h>
#include <stdint.h>

#define N_NODES 10000
#define N_EDGES 160000
#define FIN     256
#define HID     128
#define H1      5
#define H3      3
#define NGRAPH  64
#define NCLS    10
#define D1      (H1*HID)   /* 640 */
#define ETOT    (N_EDGES + N_NODES)

// ---------------- device scratch (no allocation allowed) ----------------
__device__ float g_h  [N_NODES * D1];
__device__ float g_x1 [N_NODES * D1];
__device__ float g_x2 [N_NODES * D1];
__device__ float g_agg[N_NODES * D1];
__device__ float g_als[N_NODES * H1];
__device__ float g_ald[N_NODES * H1];
__device__ float g_x3 [N_NODES * HID];
__device__ float g_pool[NGRAPH * HID];
__device__ float g_cnt [NGRAPH];
// CSR scratch
__device__ int g_deg[N_NODES];
__device__ int g_off[N_NODES + 1];
__device__ int g_cur[N_NODES];
__device__ int g_col[ETOT];

// ---------------- fills ----------------
__global__ void fill_kernel(float* p, float v, int n) {
    int i = blockIdx.x * blockDim.x + threadIdx.x;
    if (i < n) p[i] = v;
}
__global__ void fill_int_kernel(int* p, int v, int n) {
    int i = blockIdx.x * blockDim.x + threadIdx.x;
    if (i < n) p[i] = v;
}

// ---------------- CSR build: histogram -> scan -> scatter ----------------
__global__ void hist_kernel(const int* __restrict__ dst, int* __restrict__ deg) {
    int i = blockIdx.x * blockDim.x + threadIdx.x;
    if (i >= ETOT) return;
    int d = (i < N_EDGES) ? dst[i] : (i - N_EDGES);
    atomicAdd(&deg[d], 1);
}

__global__ void scan_kernel(const int* __restrict__ deg, int* __restrict__ off,
                            int* __restrict__ cur) {
    __shared__ int part[1024];
    int t = threadIdx.x;
    const int CH = (N_NODES + 1023) / 1024;   // 10
    int base = t * CH;
    int s = 0;
    for (int i = 0; i < CH; i++) {
        int idx = base + i;
        if (idx < N_NODES) s += deg[idx];
    }
    part[t] = s;
    __syncthreads();
    for (int o = 1; o < 1024; o <<= 1) {
        int v = (t >= o) ? part[t - o] : 0;
        __syncthreads();
        part[t] += v;
        __syncthreads();
    }
    int run = (t == 0) ? 0 : part[t - 1];
    for (int i = 0; i < CH; i++) {
        int idx = base + i;
        if (idx < N_NODES) {
            off[idx] = run;
            cur[idx] = run;
            run += deg[idx];
        }
    }
    if (t == 1023) off[N_NODES] = ETOT;
}

__global__ void scatter_kernel(const int* __restrict__ src, const int* __restrict__ dst,
                               int* __restrict__ cur, int* __restrict__ colarr) {
    int i = blockIdx.x * blockDim.x + threadIdx.x;
    if (i >= ETOT) return;
    int d, s;
    if (i < N_EDGES) { s = src[i]; d = dst[i]; } else { s = d = i - N_EDGES; }
    int slot = atomicAdd(&cur[d], 1);
    colarr[slot] = s;
}

// ---------------- tf32 helpers ----------------
__device__ __forceinline__ float to_tf32(float x) {
    uint32_t r;
    asm("cvt.rna.tf32.f32 %0, %1;" : "=r"(r) : "f"(x));
    return __uint_as_float(r);
}

__device__ __forceinline__ void mma_tf32(float* c, const uint32_t* a,
                                         uint32_t b0, uint32_t b1) {
    asm volatile("mma.sync.aligned.m16n8k8.row.col.f32.tf32.tf32.f32 "
        "{%0,%1,%2,%3}, {%4,%5,%6,%7}, {%8,%9}, {%0,%1,%2,%3};"
        : "+f"(c[0]), "+f"(c[1]), "+f"(c[2]), "+f"(c[3])
        : "r"(a[0]), "r"(a[1]), "r"(a[2]), "r"(a[3]), "r"(b0), "r"(b1));
}

// ---------------- tensor-core tf32 GEMM: C[M,Nd] = A[M,K] @ B[K,Nd] ----------------
// BM=BN=128, BK=16; 8 warps; warp tile 32x64; m16n8k8 tf32 mma.
// Requires Nd % 128 == 0, K % 16 == 0.
#define SSTR 136   /* smem row stride (floats): conflict-free frag loads */
__global__ void __launch_bounds__(256)
mma_gemm_kernel(const float* __restrict__ A, const float* __restrict__ B,
                float* __restrict__ C, int M, int K, int Nd) {
    __shared__ float As[16][SSTR];   // As[k][m]
    __shared__ float Bs[16][SSTR];   // Bs[k][n]
    int tid = threadIdx.x;
    int lane = tid & 31;
    int wid = tid >> 5;
    int wm = (wid & 3) * 32;   // warp row offset within block
    int wn = (wid >> 2) * 64;  // warp col offset within block
    int rowBase = blockIdx.y * 128;
    int colBase = blockIdx.x * 128;
    int g = lane >> 2, t4 = lane & 3;

    float c[2][8][4];
    #pragma unroll
    for (int mt = 0; mt < 2; mt++)
        #pragma unroll
        for (int nt = 0; nt < 8; nt++)
            #pragma unroll
            for (int i = 0; i < 4; i++) c[mt][nt][i] = 0.f;

    for (int k0 = 0; k0 < K; k0 += 16) {
        // A tile: 128 rows x 16 k  (store transposed As[k][m])
        #pragma unroll
        for (int it = 0; it < 2; it++) {
            int f = tid + it * 256;        // 0..511 float4 slots
            int row = f >> 2, q = f & 3;
            float4 a4 = make_float4(0.f, 0.f, 0.f, 0.f);
            int grow = rowBase + row;
            if (grow < M) a4 = *(const float4*)&A[(size_t)grow * K + k0 + q * 4];
            As[q * 4 + 0][row] = to_tf32(a4.x);
            As[q * 4 + 1][row] = to_tf32(a4.y);
            As[q * 4 + 2][row] = to_tf32(a4.z);
            As[q * 4 + 3][row] = to_tf32(a4.w);
        }
        // B tile: 16 k x 128 cols
        #pragma unroll
        for (int it = 0; it < 2; it++) {
            int f = tid + it * 256;
            int kr = f >> 5, c4 = (f & 31) * 4;
            float4 b4 = *(const float4*)&B[(size_t)(k0 + kr) * Nd + colBase + c4];
            b4.x = to_tf32(b4.x); b4.y = to_tf32(b4.y);
            b4.z = to_tf32(b4.z); b4.w = to_tf32(b4.w);
            *(float4*)&Bs[kr][c4] = b4;
        }
        __syncthreads();
        #pragma unroll
        for (int kk = 0; kk < 16; kk += 8) {
            uint32_t a[2][4];
            #pragma unroll
            for (int mt = 0; mt < 2; mt++) {
                int r0 = wm + mt * 16 + g;
                a[mt][0] = __float_as_uint(As[kk + t4    ][r0    ]);
                a[mt][1] = __float_as_uint(As[kk + t4    ][r0 + 8]);
                a[mt][2] = __float_as_uint(As[kk + t4 + 4][r0    ]);
                a[mt][3] = __float_as_uint(As[kk + t4 + 4][r0 + 8]);
            }
            #pragma unroll
            for (int nt = 0; nt < 8; nt++) {
                int cn = wn + nt * 8 + g;
                uint32_t b0 = __float_as_uint(Bs[kk + t4    ][cn]);
                uint32_t b1 = __float_as_uint(Bs[kk + t4 + 4][cn]);
                mma_tf32(c[0][nt], a[0], b0, b1);
                mma_tf32(c[1][nt], a[1], b0, b1);
            }
        }
        __syncthreads();
    }
    // epilogue
    #pragma unroll
    for (int mt = 0; mt < 2; mt++) {
        int r0 = rowBase + wm + mt * 16 + g;
        #pragma unroll
        for (int nt = 0; nt < 8; nt++) {
            int cc = colBase + wn + nt * 8 + (t4 << 1);
            if (r0 < M)
                *(float2*)&C[(size_t)r0 * Nd + cc] = make_float2(c[mt][nt][0], c[mt][nt][1]);
            if (r0 + 8 < M)
                *(float2*)&C[(size_t)(r0 + 8) * Nd + cc] = make_float2(c[mt][nt][2], c[mt][nt][3]);
        }
    }
}

// ---------------- per-(node,head) attention logits ----------------
__global__ void attn_logits_kernel(const float* __restrict__ h,
                                   const float* __restrict__ a_s,
                                   const float* __restrict__ a_d,
                                   float* __restrict__ als, float* __restrict__ ald,
                                   int N, int H) {
    int w = (blockIdx.x * blockDim.x + threadIdx.x) >> 5;
    int lane = threadIdx.x & 31;
    if (w >= N * H) return;
    int n = w / H, hh = w % H;
    const float* hp = h + ((size_t)n * H + hh) * HID;
    float s1 = 0.f, s2 = 0.f;
    #pragma unroll
    for (int c = lane; c < HID; c += 32) {
        float v = hp[c];
        s1 += v * a_s[hh * HID + c];
        s2 += v * a_d[hh * HID + c];
    }
    #pragma unroll
    for (int o = 16; o > 0; o >>= 1) {
        s1 += __shfl_xor_sync(0xffffffffu, s1, o);
        s2 += __shfl_xor_sync(0xffffffffu, s2, o);
    }
    if (lane == 0) { als[w] = s1; ald[w] = s2; }
}

// ---------------- CSR softmax aggregation: one warp per node ----------------
// Pass 2 computes exp once per edge (lane-strided) and broadcasts via shfl,
// eliminating the 32x-redundant MUFU.EX2 of the previous version.
__global__ void gat_agg_kernel(const int* __restrict__ off, const int* __restrict__ col,
                               const float* __restrict__ als, const float* __restrict__ ald,
                               const float* __restrict__ h, float* __restrict__ agg, int H) {
    int node = (blockIdx.x * blockDim.x + threadIdx.x) >> 5;
    int lane = threadIdx.x & 31;
    if (node >= N_NODES) return;
    int beg = off[node], end = off[node + 1];
    for (int hh = 0; hh < H; hh++) {
        float ald_d = __ldg(&ald[node * H + hh]);
        // pass 1: max (lane-strided)
        float mx = -1e30f;
        for (int j = beg + lane; j < end; j += 32) {
            float v = __ldg(&als[col[j] * H + hh]) + ald_d;
            v = v > 0.f ? v : 0.2f * v;
            mx = fmaxf(mx, v);
        }
        #pragma unroll
        for (int o = 16; o > 0; o >>= 1)
            mx = fmaxf(mx, __shfl_xor_sync(0xffffffffu, mx, o));
        // pass 2: chunk of 32 edges; each lane computes one exp, then broadcast
        float4 acc = make_float4(0.f, 0.f, 0.f, 0.f);
        float ssum = 0.f;
        for (int j0 = beg; j0 < end; j0 += 32) {
            int jj = j0 + lane;
            float ex = 0.f;
            int sc = 0;
            if (jj < end) {
                sc = col[jj];
                float v = __ldg(&als[sc * H + hh]) + ald_d;
                v = v > 0.f ? v : 0.2f * v;
                ex = __expf(v - mx);
            }
            ssum += ex;
            int cnt = end - j0; if (cnt > 32) cnt = 32;
            for (int t = 0; t < cnt; t++) {
                float exb = __shfl_sync(0xffffffffu, ex, t);
                int   sb  = __shfl_sync(0xffffffffu, sc, t);
                float4 hv = ((const float4*)(h + ((size_t)sb * H + hh) * HID))[lane];
                acc.x += exb * hv.x;
                acc.y += exb * hv.y;
                acc.z += exb * hv.z;
                acc.w += exb * hv.w;
            }
        }
        #pragma unroll
        for (int o = 16; o > 0; o >>= 1)
            ssum += __shfl_xor_sync(0xffffffffu, ssum, o);
        float inv = 1.f / (ssum + 1e-16f);
        float4 o4 = make_float4(acc.x * inv, acc.y * inv, acc.z * inv, acc.w * inv);
        ((float4*)(agg + ((size_t)node * H + hh) * HID))[lane] = o4;
    }
}

// ---------------- layer finalizers (agg already normalized) ----------------
__global__ void finalize1_kernel(const float* __restrict__ agg,
                                 const float* __restrict__ b, float* __restrict__ x1) {
    int i = blockIdx.x * blockDim.x + threadIdx.x;
    if (i >= N_NODES * D1) return;
    int r = i % D1;
    float v = agg[i] + b[r];
    x1[i] = v > 0.f ? v : (expf(v) - 1.f);   // ELU
}

__global__ void finalize2_kernel(const float* __restrict__ agg,
                                 const float* __restrict__ b, const float* __restrict__ x1,
                                 float* __restrict__ x2) {
    int i = blockIdx.x * blockDim.x + threadIdx.x;
    if (i >= N_NODES * D1) return;
    int r = i % D1;
    float v = x1[i] + agg[i] + b[r];
    x2[i] = v > 0.f ? v : (expf(v) - 1.f);
}

__global__ void finalize3_kernel(const float* __restrict__ agg,
                                 const float* __restrict__ b, float* __restrict__ x3) {
    int i = blockIdx.x * blockDim.x + threadIdx.x;
    if (i >= N_NODES * HID) return;
    int n = i / HID, c = i % HID;
    float acc = 0.f;
    #pragma unroll
    for (int hh = 0; hh < H3; hh++)
        acc += agg[((size_t)n * H3 + hh) * HID + c];
    x3[i] = acc * (1.f / 3.f) + b[c];
}

// ---------------- global mean pool ----------------
__global__ void pool_kernel(const float* __restrict__ x3, const int* __restrict__ batch,
                            float* __restrict__ pool, float* __restrict__ cnt) {
    int i = blockIdx.x * blockDim.x + threadIdx.x;
    if (i >= N_NODES * HID) return;
    int n = i / HID, c = i % HID;
    int g = batch[n];
    atomicAdd(&pool[(size_t)g * HID + c], x3[i]);
    if (c == 0) atomicAdd(&cnt[g], 1.f);
}

// ---------------- classifier head + log_softmax ----------------
__global__ void head_kernel(const float* __restrict__ pool, const float* __restrict__ cnt,
                            const float* __restrict__ Wc, const float* __restrict__ bc,
                            float* __restrict__ out) {
    __shared__ float sl[NGRAPH][NCLS];
    __shared__ float lse[NGRAPH];
    int tid = threadIdx.x;               // 640 threads
    int g = tid / NCLS, k = tid % NCLS;
    float c = cnt[g]; c = c < 1.f ? 1.f : c;
    float acc = bc[k];
    #pragma unroll 8
    for (int j = 0; j < HID; j++)
        acc += (pool[(size_t)g * HID + j] / c) * Wc[j * NCLS + k];
    sl[g][k] = acc;
    out[g * NCLS + k] = acc;             // logits
    __syncthreads();
    if (k == 0) {
        float mx = sl[g][0];
        #pragma unroll
        for (int j = 1; j < NCLS; j++) mx = fmaxf(mx, sl[g][j]);
        float s = 0.f;
        #pragma unroll
        for (int j = 0; j < NCLS; j++) s += expf(sl[g][j] - mx);
        lse[g] = mx + logf(s);
    }
    __syncthreads();
    out[NGRAPH * NCLS + g * NCLS + k] = sl[g][k] - lse[g];   // log_softmax
}

// ---------------- one GAT layer ----------------
static void run_gat(const float* X, int Din, int H, const float* W,
                    const float* as_, const float* ad_,
                    const int* off, const int* col,
                    float* h, float* agg, float* als, float* ald) {
    int D = H * HID;
    dim3 grid(D / 128, (N_NODES + 127) / 128);
    mma_gemm_kernel<<<grid, 256>>>(X, W, h, N_NODES, Din, D);
    attn_logits_kernel<<<(N_NODES * H * 32 + 255) / 256, 256>>>(h, as_, ad_, als, ald, N_NODES, H);
    gat_agg_kernel<<<(N_NODES * 32 + 255) / 256, 256>>>(off, col, als, ald, h, agg, H);
}

extern "C" void kernel_launch(void* const* d_in, const int* in_sizes, int n_in,
                              void* d_out, int out_size) {
    const float* x     = (const float*)d_in[0];
    const int*   ei    = (const int*)  d_in[1];
    const int*   batch = (const int*)  d_in[2];
    const float* W1  = (const float*)d_in[3];
    const float* a1s = (const float*)d_in[4];
    const float* a1d = (const float*)d_in[5];
    const float* b1  = (const float*)d_in[6];
    const float* W2  = (const float*)d_in[7];
    const float* a2s = (const float*)d_in[8];
    const float* a2d = (const float*)d_in[9];
    const float* b2  = (const float*)d_in[10];
    const float* W3  = (const float*)d_in[11];
    const float* a3s = (const float*)d_in[12];
    const float* a3d = (const float*)d_in[13];
    const float* b3  = (const float*)d_in[14];
    const float* Wc  = (const float*)d_in[15];
    const float* bc  = (const float*)d_in[16];
    float* out = (float*)d_out;

    float *h, *x1, *x2, *agg, *als, *ald, *x3, *pool, *cnt;
    int *deg, *off, *cur, *col;
    cudaGetSymbolAddress((void**)&h,    g_h);
    cudaGetSymbolAddress((void**)&x1,   g_x1);
    cudaGetSymbolAddress((void**)&x2,   g_x2);
    cudaGetSymbolAddress((void**)&agg,  g_agg);
    cudaGetSymbolAddress((void**)&als,  g_als);
    cudaGetSymbolAddress((void**)&ald,  g_ald);
    cudaGetSymbolAddress((void**)&x3,   g_x3);
    cudaGetSymbolAddress((void**)&pool, g_pool);
    cudaGetSymbolAddress((void**)&cnt,  g_cnt);
    cudaGetSymbolAddress((void**)&deg,  g_deg);
    cudaGetSymbolAddress((void**)&off,  g_off);
    cudaGetSymbolAddress((void**)&cur,  g_cur);
    cudaGetSymbolAddress((void**)&col,  g_col);

    const int* src = ei;
    const int* dst = ei + N_EDGES;

    // ---- CSR build (by destination) ----
    fill_int_kernel<<<(N_NODES + 255) / 256, 256>>>(deg, 0, N_NODES);
    hist_kernel<<<(ETOT + 255) / 256, 256>>>(dst, deg);
    scan_kernel<<<1, 1024>>>(deg, off, cur);
    scatter_kernel<<<(ETOT + 255) / 256, 256>>>(src, dst, cur, col);

    // Layer 1: x1 = elu(gat(x))
    run_gat(x, FIN, H1, W1, a1s, a1d, off, col, h, agg, als, ald);
    finalize1_kernel<<<(N_NODES * D1 + 255) / 256, 256>>>(agg, b1, x1);

    // Layer 2: x2 = elu(x1 + gat(x1))
    run_gat(x1, D1, H1, W2, a2s, a2d, off, col, h, agg, als, ald);
    finalize2_kernel<<<(N_NODES * D1 + 255) / 256, 256>>>(agg, b2, x1, x2);

    // Layer 3: x3 = mean-head gat(x2)
    run_gat(x2, D1, H3, W3, a3s, a3d, off, col, h, agg, als, ald);
    finalize3_kernel<<<(N_NODES * HID + 255) / 256, 256>>>(agg, b3, x3);

    // Global mean pool + head
    fill_kernel<<<(NGRAPH * HID + 255) / 256, 256>>>(pool, 0.f, NGRAPH * HID);
    fill_kernel<<<(NGRAPH + 255) / 256, 256>>>(cnt, 0.f, NGRAPH);
    pool_kernel<<<(N_NODES * HID + 255) / 256, 256>>>(x3, batch, pool, cnt);
    head_kernel<<<1, NGRAPH * NCLS>>>(pool, cnt, Wc, bc, out);
}